// round 7
// baseline (speedup 1.0000x reference)
#include <cuda_runtime.h>
#include <cstdint>

#define HH  1024
#define BB  2
#define SS  2048
#define NHH 16
#define HDD 64
#define MT  (BB*SS)   // 4096

// ---------------- scratch globals (allocation-free) ----------------
__device__ __align__(128) float g_xhi[MT*HH];
__device__ __align__(128) float g_xlo[MT*HH];
__device__ __align__(128) float g_WdThi[HH*HH];   // (Wq-Wk)^T hi, tf32-rounded
__device__ __align__(128) float g_WdTlo[HH*HH];
__device__ __align__(128) float g_WvT[HH*HH];     // Wv^T tf32-rounded
__device__ __align__(128) float g_WoT[HH*HH];     // Wo^T tf32-rounded
__device__ __align__(128) float g_bd[HH];
__device__ __align__(128) float g_Dhi[MT*HH];     // tf32(D)
__device__ __align__(128) float g_Dlo[MT*HH];     // tf32(D - tf32(D))
__device__ __align__(128) float g_V[MT*HH];       // tf32-rounded V (bias incl.)
__device__ __align__(128) float g_C[MT*HH];       // tf32-rounded attention ctx

// ---------------- helpers ----------------
__device__ __forceinline__ float tfr(float x) {
    uint32_t r;
    asm("cvt.rna.tf32.f32 %0, %1;" : "=r"(r) : "f"(x));
    return __uint_as_float(r);
}
__device__ __forceinline__ void cp16(float* s, const float* g) {
    uint32_t sa = (uint32_t)__cvta_generic_to_shared(s);
    asm volatile("cp.async.cg.shared.global [%0], [%1], 16;" :: "r"(sa), "l"(g));
}
__device__ __forceinline__ void cp_commit() { asm volatile("cp.async.commit_group;"); }
template<int N> __device__ __forceinline__ void cp_wait() {
    asm volatile("cp.async.wait_group %0;" :: "n"(N));
}
__device__ __forceinline__ void mma8(float* d, const uint32_t* a, uint32_t b0, uint32_t b1) {
    asm volatile(
        "mma.sync.aligned.m16n8k8.row.col.f32.tf32.tf32.f32 "
        "{%0,%1,%2,%3},{%4,%5,%6,%7},{%8,%9},{%0,%1,%2,%3};"
        : "+f"(d[0]), "+f"(d[1]), "+f"(d[2]), "+f"(d[3])
        : "r"(a[0]), "r"(a[1]), "r"(a[2]), "r"(a[3]), "r"(b0), "r"(b1));
}

// ---------------- prep: x -> hi/lo planes; bd = bq-bk ----------------
__global__ void prep_x(const float* __restrict__ x,
                       const float* __restrict__ bq, const float* __restrict__ bk) {
    int i = blockIdx.x * 256 + threadIdx.x;
    float v = x[i];
    float hi = tfr(v);
    g_xhi[i] = hi;
    g_xlo[i] = tfr(v - hi);
    if (i < HH) g_bd[i] = bq[i] - bk[i];
}

// ---------------- prep: transpose + tf32-convert weights ----------------
__global__ void prep_w(const float* __restrict__ Wq, const float* __restrict__ Wk,
                       const float* __restrict__ Wv, const float* __restrict__ Wo) {
    __shared__ float t0[32][33];
    __shared__ float t1[32][33];
    const int z = blockIdx.z;
    const int c0 = blockIdx.x * 32, r0 = blockIdx.y * 32;
    const int tx = threadIdx.x & 31, ty = threadIdx.x >> 5;
    #pragma unroll
    for (int rr = ty; rr < 32; rr += 8) {
        int idx = (r0 + rr) * HH + c0 + tx;
        if (z == 0) {
            float v = Wq[idx] - Wk[idx];
            float hi = tfr(v);
            t0[rr][tx] = hi;
            t1[rr][tx] = tfr(v - hi);
        } else if (z == 1) t0[rr][tx] = tfr(Wv[idx]);
        else               t0[rr][tx] = tfr(Wo[idx]);
    }
    __syncthreads();
    #pragma unroll
    for (int rr = ty; rr < 32; rr += 8) {
        int odx = (c0 + rr) * HH + r0 + tx;   // transposed
        if (z == 0) { g_WdThi[odx] = t0[tx][rr]; g_WdTlo[odx] = t1[tx][rr]; }
        else if (z == 1) g_WvT[odx] = t0[tx][rr];
        else             g_WoT[odx] = t0[tx][rr];
    }
}

// ---------------- tf32 GEMM (plain): C = A @ BT^T + bias.  BK=16, 3-stage ----------------
#define GP 20
template<bool ROUND>
__global__ __launch_bounds__(256, 2) void gemm_plain(
    const float* __restrict__ A, const float* __restrict__ BT,
    const float* __restrict__ bias, float* __restrict__ C)
{
    extern __shared__ float sm[];
    const int K = HH, N = HH;
    const int tid = threadIdx.x, w = tid >> 5, lane = tid & 31;
    const int g = lane >> 2, t = lane & 3;
    const int wm = (w & 3) * 32, wn = (w >> 2) * 64;
    const int rowBase = blockIdx.y * 128, colBase = blockIdx.x * 128;
    const int lr = tid >> 1, lc = (tid & 1) * 8;

    const float* pA = A  + (size_t)(rowBase + lr) * K + lc;
    const float* pB = BT + (size_t)(colBase + lr) * K + lc;

    float acc[2][8][4];
    #pragma unroll
    for (int mt = 0; mt < 2; mt++)
        #pragma unroll
        for (int nt = 0; nt < 8; nt++)
            #pragma unroll
            for (int q = 0; q < 4; q++) acc[mt][nt][q] = 0.f;

    const int NIT = K / 16;   // 64
    const int off = lr * GP + lc;
    auto issue = [&](int it, int s) {
        float* base = sm + s * 2 * 128 * GP;
        const float* gA = pA + it * 16;
        const float* gB = pB + it * 16;
        cp16(base + off,               gA);
        cp16(base + off + 4,           gA + 4);
        cp16(base + 128*GP + off,      gB);
        cp16(base + 128*GP + off + 4,  gB + 4);
    };
    issue(0, 0); cp_commit();
    issue(1, 1); cp_commit();

    for (int i = 0; i < NIT; i++) {
        cp_wait<1>();
        __syncthreads();
        if (i + 2 < NIT) { issue(i + 2, (i + 2) % 3); }
        cp_commit();
        const float* base = sm + (i % 3) * 2 * 128 * GP;
        const float* sA = base;
        const float* sB = base + 128 * GP;
        #pragma unroll
        for (int kk = 0; kk < 2; kk++) {
            const int ko = kk * 8;
            uint32_t a[2][4];
            #pragma unroll
            for (int mt = 0; mt < 2; mt++) {
                int r = wm + mt * 16 + g;
                a[mt][0] = __float_as_uint(sA[r * GP + ko + t]);
                a[mt][1] = __float_as_uint(sA[(r + 8) * GP + ko + t]);
                a[mt][2] = __float_as_uint(sA[r * GP + ko + t + 4]);
                a[mt][3] = __float_as_uint(sA[(r + 8) * GP + ko + t + 4]);
            }
            #pragma unroll
            for (int nt = 0; nt < 8; nt++) {
                int c = wn + nt * 8 + g;
                uint32_t b0 = __float_as_uint(sB[c * GP + ko + t]);
                uint32_t b1 = __float_as_uint(sB[c * GP + ko + t + 4]);
                mma8(acc[0][nt], a[0], b0, b1);
                mma8(acc[1][nt], a[1], b0, b1);
            }
        }
    }

    #pragma unroll
    for (int mt = 0; mt < 2; mt++)
        #pragma unroll
        for (int nt = 0; nt < 8; nt++) {
            int row = rowBase + wm + mt * 16 + g;
            int col = colBase + wn + nt * 8 + 2 * t;
            float2 bb = *(const float2*)(bias + col);
            float v00 = acc[mt][nt][0] + bb.x, v01 = acc[mt][nt][1] + bb.y;
            float v10 = acc[mt][nt][2] + bb.x, v11 = acc[mt][nt][3] + bb.y;
            if (ROUND) { v00 = tfr(v00); v01 = tfr(v01); v10 = tfr(v10); v11 = tfr(v11); }
            *(float2*)(C + (size_t)row * N + col)       = make_float2(v00, v01);
            *(float2*)(C + (size_t)(row + 8) * N + col) = make_float2(v10, v11);
        }
}

// ---------------- tf32x2 split GEMM for D.  BK=16, 2-stage ----------------
__global__ __launch_bounds__(256, 2) void gemm_split(
    const float* __restrict__ Ah, const float* __restrict__ Al,
    const float* __restrict__ Bh, const float* __restrict__ Bl,
    const float* __restrict__ bias,
    float* __restrict__ Chi, float* __restrict__ Clo)
{
    extern __shared__ float sm[];
    const int K = HH, N = HH;
    const int tid = threadIdx.x, w = tid >> 5, lane = tid & 31;
    const int g = lane >> 2, t = lane & 3;
    const int wm = (w & 3) * 32, wn = (w >> 2) * 64;
    const int rowBase = blockIdx.y * 128, colBase = blockIdx.x * 128;
    const int lr = tid >> 1, lc = (tid & 1) * 8;

    const float* pAh = Ah + (size_t)(rowBase + lr) * K + lc;
    const float* pAl = Al + (size_t)(rowBase + lr) * K + lc;
    const float* pBh = Bh + (size_t)(colBase + lr) * K + lc;
    const float* pBl = Bl + (size_t)(colBase + lr) * K + lc;

    float acc[2][8][4];
    #pragma unroll
    for (int mt = 0; mt < 2; mt++)
        #pragma unroll
        for (int nt = 0; nt < 8; nt++)
            #pragma unroll
            for (int q = 0; q < 4; q++) acc[mt][nt][q] = 0.f;

    const int NIT = K / 16;   // 64
    const int off = lr * GP + lc;
    auto issue = [&](int it, int s) {
        float* base = sm + s * 4 * 128 * GP;
        const float* gAh = pAh + it * 16;
        const float* gAl = pAl + it * 16;
        const float* gBh = pBh + it * 16;
        const float* gBl = pBl + it * 16;
        cp16(base + off,                 gAh);
        cp16(base + off + 4,             gAh + 4);
        cp16(base + 128*GP + off,        gAl);
        cp16(base + 128*GP + off + 4,    gAl + 4);
        cp16(base + 2*128*GP + off,      gBh);
        cp16(base + 2*128*GP + off + 4,  gBh + 4);
        cp16(base + 3*128*GP + off,      gBl);
        cp16(base + 3*128*GP + off + 4,  gBl + 4);
    };
    issue(0, 0); cp_commit();

    for (int i = 0; i < NIT; i++) {
        cp_wait<0>();
        __syncthreads();
        if (i + 1 < NIT) { issue(i + 1, (i + 1) & 1); }
        cp_commit();
        const float* base = sm + (i & 1) * 4 * 128 * GP;
        const float* sAh = base;
        const float* sAl = base + 128 * GP;
        const float* sBh = base + 2 * 128 * GP;
        const float* sBl = base + 3 * 128 * GP;
        #pragma unroll
        for (int kk = 0; kk < 2; kk++) {
            const int ko = kk * 8;
            uint32_t ah[2][4], al[2][4];
            #pragma unroll
            for (int mt = 0; mt < 2; mt++) {
                int r = wm + mt * 16 + g;
                ah[mt][0] = __float_as_uint(sAh[r * GP + ko + t]);
                ah[mt][1] = __float_as_uint(sAh[(r + 8) * GP + ko + t]);
                ah[mt][2] = __float_as_uint(sAh[r * GP + ko + t + 4]);
                ah[mt][3] = __float_as_uint(sAh[(r + 8) * GP + ko + t + 4]);
                al[mt][0] = __float_as_uint(sAl[r * GP + ko + t]);
                al[mt][1] = __float_as_uint(sAl[(r + 8) * GP + ko + t]);
                al[mt][2] = __float_as_uint(sAl[r * GP + ko + t + 4]);
                al[mt][3] = __float_as_uint(sAl[(r + 8) * GP + ko + t + 4]);
            }
            #pragma unroll
            for (int nt = 0; nt < 8; nt++) {
                int c = wn + nt * 8 + g;
                uint32_t bh0 = __float_as_uint(sBh[c * GP + ko + t]);
                uint32_t bh1 = __float_as_uint(sBh[c * GP + ko + t + 4]);
                uint32_t bl0 = __float_as_uint(sBl[c * GP + ko + t]);
                uint32_t bl1 = __float_as_uint(sBl[c * GP + ko + t + 4]);
                #pragma unroll
                for (int mt = 0; mt < 2; mt++) {
                    mma8(acc[mt][nt], ah[mt], bh0, bh1);
                    mma8(acc[mt][nt], ah[mt], bl0, bl1);
                    mma8(acc[mt][nt], al[mt], bh0, bh1);
                }
            }
        }
    }

    #pragma unroll
    for (int mt = 0; mt < 2; mt++)
        #pragma unroll
        for (int nt = 0; nt < 8; nt++) {
            int row = rowBase + wm + mt * 16 + g;
            int col = colBase + wn + nt * 8 + 2 * t;
            float2 bb = *(const float2*)(bias + col);
            float v00 = acc[mt][nt][0] + bb.x, v01 = acc[mt][nt][1] + bb.y;
            float v10 = acc[mt][nt][2] + bb.x, v11 = acc[mt][nt][3] + bb.y;
            float h00 = tfr(v00), h01 = tfr(v01), h10 = tfr(v10), h11 = tfr(v11);
            size_t r0 = (size_t)row * N, r1 = (size_t)(row + 8) * N;
            *(float2*)(Chi + r0 + col) = make_float2(h00, h01);
            *(float2*)(Chi + r1 + col) = make_float2(h10, h11);
            *(float2*)(Clo + r0 + col) = make_float2(tfr(v00 - h00), tfr(v01 - h01));
            *(float2*)(Clo + r1 + col) = make_float2(tfr(v10 - h10), tfr(v11 - h11));
        }
}

// ---------------- attention: 128-q rows, 512 threads, 2 barriers/j-tile ----------------
// warp w: rows (w&7)*16, cols (w>>3)*32. Dq-hi in regs, Dq-lo persistent smem,
// S in its own smem region (no overlay). Issue-after-barrier double buffering.
#define PK 68
#define PPV 72
#define ASTG (64*PK*2 + 64*PPV)      // 13312 floats per stage
#define DQLO (2*ASTG)                // Dq-lo tile (128*PK)
#define SOFF (DQLO + 128*PK)         // S tile (128*PK)
__global__ __launch_bounds__(512, 1) void attn_mma() {
    extern __shared__ float sm[];
    const int tid = threadIdx.x, w = tid >> 5, lane = tid & 31;
    const int g = lane >> 2, t = lane & 3;
    const int mrow = (w & 7) * 16, ncol = (w >> 3) * 32;
    const int qt = blockIdx.x, bh = blockIdx.y;
    const int b = bh >> 4, h = bh & 15, q0 = qt * 128;

    const size_t base = (size_t)b * SS * HH + h * HDD;
    const float* Dh = g_Dhi + base;
    const float* Dl = g_Dlo + base;
    const float* Vp = g_V + base;
    float* sDqlo = sm + DQLO;
    float* sS    = sm + SOFF;

    // persistent Dq-lo tile: 128 x 64
    {
        const int lr2 = tid >> 2, lc2 = (tid & 3) * 16;
        const float* src = Dl + (size_t)(q0 + lr2) * HH + lc2;
        #pragma unroll
        for (int u = 0; u < 16; u += 4)
            *(float4*)&sDqlo[lr2 * PK + lc2 + u] = *(const float4*)(src + u);
    }

    // Dq-hi fragments in registers
    uint32_t qhi[8][4];
    {
        const size_t r0g = (size_t)(q0 + mrow + g) * HH;
        const size_t r1g = (size_t)(q0 + mrow + g + 8) * HH;
        #pragma unroll
        for (int c = 0; c < 8; c++) {
            int o = c * 8;
            qhi[c][0] = __float_as_uint(Dh[r0g + o + t]);
            qhi[c][1] = __float_as_uint(Dh[r1g + o + t]);
            qhi[c][2] = __float_as_uint(Dh[r0g + o + t + 4]);
            qhi[c][3] = __float_as_uint(Dh[r1g + o + t + 4]);
        }
    }

    float oacc[4][4];
    #pragma unroll
    for (int i = 0; i < 4; i++)
        #pragma unroll
        for (int j = 0; j < 4; j++) oacc[i][j] = 0.f;

    const int lr = tid >> 3, lc8 = (tid & 7) * 8;
    auto issue = [&](int jt, int s) {
        float* st = sm + s * ASTG;
        const float* srcH = Dh + (size_t)(jt * 64 + lr) * HH + lc8;
        const float* srcL = Dl + (size_t)(jt * 64 + lr) * HH + lc8;
        const float* srcV = Vp + (size_t)(jt * 64 + lr) * HH + lc8;
        cp16(st + lr * PK + lc8,                srcH);
        cp16(st + lr * PK + lc8 + 4,            srcH + 4);
        cp16(st + 64*PK + lr * PK + lc8,        srcL);
        cp16(st + 64*PK + lr * PK + lc8 + 4,    srcL + 4);
        cp16(st + 2*64*PK + lr * PPV + lc8,     srcV);
        cp16(st + 2*64*PK + lr * PPV + lc8 + 4, srcV + 4);
    };

    const int jt0 = 2 * qt;
    int buf = 0;
    issue(jt0, 0); cp_commit();
    for (int jt = jt0; jt < SS / 64; jt++) {
        cp_wait<0>();
        __syncthreads();   // stage data ready; all warps past prev PV (S + peer buf free)
        if (jt + 1 < SS / 64) { issue(jt + 1, buf ^ 1); }
        cp_commit();
        const float* st  = sm + buf * ASTG;
        const float* sKh = st;
        const float* sKl = st + 64 * PK;
        const float* sV  = st + 2 * 64 * PK;
        const int j0 = jt * 64;

        // score = Dq@Dk^T (3-mma tf32x2)
        float sacc[4][4];
        #pragma unroll
        for (int i = 0; i < 4; i++)
            #pragma unroll
            for (int j = 0; j < 4; j++) sacc[i][j] = 0.f;

        #pragma unroll
        for (int c = 0; c < 8; c++) {
            int o = c * 8;
            uint32_t ql[4];
            ql[0] = __float_as_uint(sDqlo[(mrow + g) * PK + o + t]);
            ql[1] = __float_as_uint(sDqlo[(mrow + g + 8) * PK + o + t]);
            ql[2] = __float_as_uint(sDqlo[(mrow + g) * PK + o + t + 4]);
            ql[3] = __float_as_uint(sDqlo[(mrow + g + 8) * PK + o + t + 4]);
            #pragma unroll
            for (int nt = 0; nt < 4; nt++) {
                int jr = (ncol + nt * 8 + g) * PK;
                uint32_t bh0 = __float_as_uint(sKh[jr + o + t]);
                uint32_t bh1 = __float_as_uint(sKh[jr + o + t + 4]);
                uint32_t bl0 = __float_as_uint(sKl[jr + o + t]);
                uint32_t bl1 = __float_as_uint(sKl[jr + o + t + 4]);
                mma8(sacc[nt], qhi[c], bh0, bh1);
                mma8(sacc[nt], qhi[c], bl0, bl1);
                mma8(sacc[nt], ql,     bh0, bh1);
            }
        }

        // mask (strict upper) + exp + pre-round, write S (own region, own rows)
        const int r0 = q0 + mrow + g;
        #pragma unroll
        for (int nt = 0; nt < 4; nt++) {
            int colb = j0 + ncol + nt * 8 + 2 * t;
            float s0 = (colb     > r0    ) ? tfr(__expf(-0.5f * sacc[nt][0])) : 0.f;
            float s1 = (colb + 1 > r0    ) ? tfr(__expf(-0.5f * sacc[nt][1])) : 0.f;
            float s2 = (colb     > r0 + 8) ? tfr(__expf(-0.5f * sacc[nt][2])) : 0.f;
            float s3 = (colb + 1 > r0 + 8) ? tfr(__expf(-0.5f * sacc[nt][3])) : 0.f;
            int cb = ncol + nt * 8 + 2 * t;
            *(float2*)&sS[(mrow + g) * PK + cb]     = make_float2(s0, s1);
            *(float2*)&sS[(mrow + g + 8) * PK + cb] = make_float2(s2, s3);
        }
        __syncthreads();   // S complete across warps

        // PV: oacc += S @ V  (plain tf32)
        #pragma unroll
        for (int c = 0; c < 8; c++) {
            int k = c * 8;
            uint32_t a[4];
            a[0] = __float_as_uint(sS[(mrow + g) * PK + k + t]);
            a[1] = __float_as_uint(sS[(mrow + g + 8) * PK + k + t]);
            a[2] = __float_as_uint(sS[(mrow + g) * PK + k + t + 4]);
            a[3] = __float_as_uint(sS[(mrow + g + 8) * PK + k + t + 4]);
            #pragma unroll
            for (int nt = 0; nt < 4; nt++) {
                int dbc = ncol + nt * 8;
                uint32_t b0 = __float_as_uint(sV[(k + t) * PPV + dbc + g]);
                uint32_t b1 = __float_as_uint(sV[(k + t + 4) * PPV + dbc + g]);
                mma8(oacc[nt], a, b0, b1);
            }
        }
        buf ^= 1;
    }

    // write ctx pre-rounded (O GEMM consumes tf32 directly)
    float* Cb = g_C + base;
    #pragma unroll
    for (int nt = 0; nt < 4; nt++) {
        int col = ncol + nt * 8 + 2 * t;
        *(float2*)(Cb + (size_t)(q0 + mrow + g) * HH + col) =
            make_float2(tfr(oacc[nt][0]), tfr(oacc[nt][1]));
        *(float2*)(Cb + (size_t)(q0 + mrow + g + 8) * HH + col) =
            make_float2(tfr(oacc[nt][2]), tfr(oacc[nt][3]));
    }
}

// ---------------------------------------------------------------------------
extern "C" void kernel_launch(void* const* d_in, const int* in_sizes, int n_in,
                              void* d_out, int out_size) {
    const float* x  = (const float*)d_in[0];
    const float* Wq = (const float*)d_in[1];
    const float* bq = (const float*)d_in[2];
    const float* Wk = (const float*)d_in[3];
    const float* bk = (const float*)d_in[4];
    const float* Wv = (const float*)d_in[5];
    const float* bv = (const float*)d_in[6];
    const float* Wo = (const float*)d_in[7];
    const float* bo = (const float*)d_in[8];
    float* out = (float*)d_out;

    float *pxhi, *pxlo, *pWdThi, *pWdTlo, *pWvT, *pWoT, *pbd, *pDhi, *pDlo, *pV, *pC;
    cudaGetSymbolAddress((void**)&pxhi, g_xhi);
    cudaGetSymbolAddress((void**)&pxlo, g_xlo);
    cudaGetSymbolAddress((void**)&pWdThi, g_WdThi);
    cudaGetSymbolAddress((void**)&pWdTlo, g_WdTlo);
    cudaGetSymbolAddress((void**)&pWvT, g_WvT);
    cudaGetSymbolAddress((void**)&pWoT, g_WoT);
    cudaGetSymbolAddress((void**)&pbd, g_bd);
    cudaGetSymbolAddress((void**)&pDhi, g_Dhi);
    cudaGetSymbolAddress((void**)&pDlo, g_Dlo);
    cudaGetSymbolAddress((void**)&pV, g_V);
    cudaGetSymbolAddress((void**)&pC, g_C);

    const int smem_plain = 3 * 2 * 128 * GP * sizeof(float);          // 61440
    const int smem_split = 2 * 4 * 128 * GP * sizeof(float);          // 81920
    const int smem_attn  = (2 * ASTG + 2 * 128 * PK) * sizeof(float); // 176128
    static bool attr_set = false;
    if (!attr_set) {
        cudaFuncSetAttribute(gemm_split, cudaFuncAttributeMaxDynamicSharedMemorySize, smem_split);
        cudaFuncSetAttribute(gemm_plain<true>,  cudaFuncAttributeMaxDynamicSharedMemorySize, smem_plain);
        cudaFuncSetAttribute(gemm_plain<false>, cudaFuncAttributeMaxDynamicSharedMemorySize, smem_plain);
        cudaFuncSetAttribute(attn_mma, cudaFuncAttributeMaxDynamicSharedMemorySize, smem_attn);
        attr_set = true;
    }

    prep_x<<<MT*HH/256, 256>>>(x, bq, bk);
    prep_w<<<dim3(32, 32, 3), 256>>>(Wq, Wk, Wv, Wo);

    dim3 gg(HH/128, MT/128);  // (8, 32)
    gemm_split<<<gg, 256, smem_split>>>(pxhi, pxlo, pWdThi, pWdTlo, pbd, pDhi, pDlo);
    gemm_plain<true><<<gg, 256, smem_plain>>>(pxhi, pWvT, bv, pV);

    attn_mma<<<dim3(SS/128, BB*NHH), 512, smem_attn>>>();

    gemm_plain<false><<<gg, 256, smem_plain>>>(pC, pWoT, bo, out);
}

// round 9
// speedup vs baseline: 1.0437x; 1.0437x over previous
#include <cuda_runtime.h>
#include <cstdint>

#define HH  1024
#define BB  2
#define SS  2048
#define NHH 16
#define HDD 64
#define MT  (BB*SS)   // 4096

// ---------------- scratch globals (allocation-free) ----------------
__device__ __align__(128) float g_xhi[MT*HH];
__device__ __align__(128) float g_xlo[MT*HH];
__device__ __align__(128) float g_WdThi[HH*HH];   // (Wq-Wk)^T hi, tf32-rounded
__device__ __align__(128) float g_WdTlo[HH*HH];
__device__ __align__(128) float g_WvT[HH*HH];     // Wv^T tf32-rounded
__device__ __align__(128) float g_WoT[HH*HH];     // Wo^T tf32-rounded
__device__ __align__(128) float g_bd[HH];
__device__ __align__(128) float g_Dhi[MT*HH];     // tf32(D)
__device__ __align__(128) float g_Dlo[MT*HH];     // tf32(D - tf32(D))
__device__ __align__(128) float g_V[MT*HH];       // tf32-rounded V (bias incl.)
__device__ __align__(128) float g_C[MT*HH];       // tf32-rounded attention ctx

// ---------------- helpers ----------------
__device__ __forceinline__ float tfr(float x) {
    uint32_t r;
    asm("cvt.rna.tf32.f32 %0, %1;" : "=r"(r) : "f"(x));
    return __uint_as_float(r);
}
__device__ __forceinline__ void cp16(float* s, const float* g) {
    uint32_t sa = (uint32_t)__cvta_generic_to_shared(s);
    asm volatile("cp.async.cg.shared.global [%0], [%1], 16;" :: "r"(sa), "l"(g));
}
__device__ __forceinline__ void cp_commit() { asm volatile("cp.async.commit_group;"); }
template<int N> __device__ __forceinline__ void cp_wait() {
    asm volatile("cp.async.wait_group %0;" :: "n"(N));
}
__device__ __forceinline__ void mma8(float* d, const uint32_t* a, uint32_t b0, uint32_t b1) {
    asm volatile(
        "mma.sync.aligned.m16n8k8.row.col.f32.tf32.tf32.f32 "
        "{%0,%1,%2,%3},{%4,%5,%6,%7},{%8,%9},{%0,%1,%2,%3};"
        : "+f"(d[0]), "+f"(d[1]), "+f"(d[2]), "+f"(d[3])
        : "r"(a[0]), "r"(a[1]), "r"(a[2]), "r"(a[3]), "r"(b0), "r"(b1));
}

// ---------------- prep: x -> hi/lo planes; bd = bq-bk ----------------
__global__ void prep_x(const float* __restrict__ x,
                       const float* __restrict__ bq, const float* __restrict__ bk) {
    int i = blockIdx.x * 256 + threadIdx.x;
    float v = x[i];
    float hi = tfr(v);
    g_xhi[i] = hi;
    g_xlo[i] = tfr(v - hi);
    if (i < HH) g_bd[i] = bq[i] - bk[i];
}

// ---------------- prep: transpose + tf32-convert weights ----------------
__global__ void prep_w(const float* __restrict__ Wq, const float* __restrict__ Wk,
                       const float* __restrict__ Wv, const float* __restrict__ Wo) {
    __shared__ float t0[32][33];
    __shared__ float t1[32][33];
    const int z = blockIdx.z;
    const int c0 = blockIdx.x * 32, r0 = blockIdx.y * 32;
    const int tx = threadIdx.x & 31, ty = threadIdx.x >> 5;
    #pragma unroll
    for (int rr = ty; rr < 32; rr += 8) {
        int idx = (r0 + rr) * HH + c0 + tx;
        if (z == 0) {
            float v = Wq[idx] - Wk[idx];
            float hi = tfr(v);
            t0[rr][tx] = hi;
            t1[rr][tx] = tfr(v - hi);
        } else if (z == 1) t0[rr][tx] = tfr(Wv[idx]);
        else               t0[rr][tx] = tfr(Wo[idx]);
    }
    __syncthreads();
    #pragma unroll
    for (int rr = ty; rr < 32; rr += 8) {
        int odx = (c0 + rr) * HH + r0 + tx;   // transposed
        if (z == 0) { g_WdThi[odx] = t0[tx][rr]; g_WdTlo[odx] = t1[tx][rr]; }
        else if (z == 1) g_WvT[odx] = t0[tx][rr];
        else             g_WoT[odx] = t0[tx][rr];
    }
}

// ---------------- tf32 GEMM (plain): C = A @ BT^T + bias.  BK=8, 3-stage ----------------
#define GP 12
template<bool ROUND>
__global__ __launch_bounds__(256, 2) void gemm_plain(
    const float* __restrict__ A, const float* __restrict__ BT,
    const float* __restrict__ bias, float* __restrict__ C)
{
    extern __shared__ float sm[];
    const int K = HH, N = HH;
    const int tid = threadIdx.x, w = tid >> 5, lane = tid & 31;
    const int g = lane >> 2, t = lane & 3;
    const int wm = (w & 3) * 32, wn = (w >> 2) * 64;
    const int rowBase = blockIdx.y * 128, colBase = blockIdx.x * 128;
    const int lr = tid >> 1, lc = (tid & 1) * 4;

    const float* pA = A  + (size_t)(rowBase + lr) * K + lc;
    const float* pB = BT + (size_t)(colBase + lr) * K + lc;

    float acc[2][8][4];
    #pragma unroll
    for (int mt = 0; mt < 2; mt++)
        #pragma unroll
        for (int nt = 0; nt < 8; nt++)
            #pragma unroll
            for (int q = 0; q < 4; q++) acc[mt][nt][q] = 0.f;

    const int NIT = K / 8;
    const int off = lr * GP + lc;
    auto issue = [&](int it, int s) {
        float* base = sm + s * 2 * 128 * GP;
        cp16(base + off,          pA + it * 8);
        cp16(base + 128*GP + off, pB + it * 8);
    };
    issue(0, 0); cp_commit();
    issue(1, 1); cp_commit();

    for (int i = 0; i < NIT; i++) {
        cp_wait<1>();
        __syncthreads();
        const float* base = sm + (i % 3) * 2 * 128 * GP;
        const float* sA = base;
        const float* sB = base + 128 * GP;
        uint32_t a[2][4];
        #pragma unroll
        for (int mt = 0; mt < 2; mt++) {
            int r = wm + mt * 16 + g;
            a[mt][0] = __float_as_uint(sA[r * GP + t]);
            a[mt][1] = __float_as_uint(sA[(r + 8) * GP + t]);
            a[mt][2] = __float_as_uint(sA[r * GP + t + 4]);
            a[mt][3] = __float_as_uint(sA[(r + 8) * GP + t + 4]);
        }
        #pragma unroll
        for (int nt = 0; nt < 8; nt++) {
            int c = wn + nt * 8 + g;
            uint32_t b0 = __float_as_uint(sB[c * GP + t]);
            uint32_t b1 = __float_as_uint(sB[c * GP + t + 4]);
            mma8(acc[0][nt], a[0], b0, b1);
            mma8(acc[1][nt], a[1], b0, b1);
        }
        if (i + 2 < NIT) issue(i + 2, (i + 2) % 3);
        cp_commit();
    }

    #pragma unroll
    for (int mt = 0; mt < 2; mt++)
        #pragma unroll
        for (int nt = 0; nt < 8; nt++) {
            int row = rowBase + wm + mt * 16 + g;
            int col = colBase + wn + nt * 8 + 2 * t;
            float2 bb = *(const float2*)(bias + col);
            float v00 = acc[mt][nt][0] + bb.x, v01 = acc[mt][nt][1] + bb.y;
            float v10 = acc[mt][nt][2] + bb.x, v11 = acc[mt][nt][3] + bb.y;
            if (ROUND) { v00 = tfr(v00); v01 = tfr(v01); v10 = tfr(v10); v11 = tfr(v11); }
            *(float2*)(C + (size_t)row * N + col)       = make_float2(v00, v01);
            *(float2*)(C + (size_t)(row + 8) * N + col) = make_float2(v10, v11);
        }
}

// ---------------- tf32x2 split GEMM for D; writes hi/lo planes.  BK=8, 3-stage ----------------
__global__ __launch_bounds__(256, 2) void gemm_split(
    const float* __restrict__ Ah, const float* __restrict__ Al,
    const float* __restrict__ Bh, const float* __restrict__ Bl,
    const float* __restrict__ bias,
    float* __restrict__ Chi, float* __restrict__ Clo)
{
    extern __shared__ float sm[];
    const int K = HH, N = HH;
    const int tid = threadIdx.x, w = tid >> 5, lane = tid & 31;
    const int g = lane >> 2, t = lane & 3;
    const int wm = (w & 3) * 32, wn = (w >> 2) * 64;
    const int rowBase = blockIdx.y * 128, colBase = blockIdx.x * 128;
    const int lr = tid >> 1, lc = (tid & 1) * 4;

    const float* pAh = Ah + (size_t)(rowBase + lr) * K + lc;
    const float* pAl = Al + (size_t)(rowBase + lr) * K + lc;
    const float* pBh = Bh + (size_t)(colBase + lr) * K + lc;
    const float* pBl = Bl + (size_t)(colBase + lr) * K + lc;

    float acc[2][8][4];
    #pragma unroll
    for (int mt = 0; mt < 2; mt++)
        #pragma unroll
        for (int nt = 0; nt < 8; nt++)
            #pragma unroll
            for (int q = 0; q < 4; q++) acc[mt][nt][q] = 0.f;

    const int NIT = K / 8;
    const int off = lr * GP + lc;
    auto issue = [&](int it, int s) {
        float* base = sm + s * 4 * 128 * GP;
        cp16(base + off,            pAh + it * 8);
        cp16(base + 128*GP   + off, pAl + it * 8);
        cp16(base + 2*128*GP + off, pBh + it * 8);
        cp16(base + 3*128*GP + off, pBl + it * 8);
    };
    issue(0, 0); cp_commit();
    issue(1, 1); cp_commit();

    for (int i = 0; i < NIT; i++) {
        cp_wait<1>();
        __syncthreads();
        const float* base = sm + (i % 3) * 4 * 128 * GP;
        const float* sAh = base;
        const float* sAl = base + 128 * GP;
        const float* sBh = base + 2 * 128 * GP;
        const float* sBl = base + 3 * 128 * GP;
        uint32_t ah[2][4], al[2][4];
        #pragma unroll
        for (int mt = 0; mt < 2; mt++) {
            int r = wm + mt * 16 + g;
            ah[mt][0] = __float_as_uint(sAh[r * GP + t]);
            ah[mt][1] = __float_as_uint(sAh[(r + 8) * GP + t]);
            ah[mt][2] = __float_as_uint(sAh[r * GP + t + 4]);
            ah[mt][3] = __float_as_uint(sAh[(r + 8) * GP + t + 4]);
            al[mt][0] = __float_as_uint(sAl[r * GP + t]);
            al[mt][1] = __float_as_uint(sAl[(r + 8) * GP + t]);
            al[mt][2] = __float_as_uint(sAl[r * GP + t + 4]);
            al[mt][3] = __float_as_uint(sAl[(r + 8) * GP + t + 4]);
        }
        #pragma unroll
        for (int nt = 0; nt < 8; nt++) {
            int c = wn + nt * 8 + g;
            uint32_t bh0 = __float_as_uint(sBh[c * GP + t]);
            uint32_t bh1 = __float_as_uint(sBh[c * GP + t + 4]);
            uint32_t bl0 = __float_as_uint(sBl[c * GP + t]);
            uint32_t bl1 = __float_as_uint(sBl[c * GP + t + 4]);
            #pragma unroll
            for (int mt = 0; mt < 2; mt++) {
                mma8(acc[mt][nt], ah[mt], bh0, bh1);
                mma8(acc[mt][nt], ah[mt], bl0, bl1);
                mma8(acc[mt][nt], al[mt], bh0, bh1);
            }
        }
        if (i + 2 < NIT) issue(i + 2, (i + 2) % 3);
        cp_commit();
    }

    #pragma unroll
    for (int mt = 0; mt < 2; mt++)
        #pragma unroll
        for (int nt = 0; nt < 8; nt++) {
            int row = rowBase + wm + mt * 16 + g;
            int col = colBase + wn + nt * 8 + 2 * t;
            float2 bb = *(const float2*)(bias + col);
            float v00 = acc[mt][nt][0] + bb.x, v01 = acc[mt][nt][1] + bb.y;
            float v10 = acc[mt][nt][2] + bb.x, v11 = acc[mt][nt][3] + bb.y;
            float h00 = tfr(v00), h01 = tfr(v01), h10 = tfr(v10), h11 = tfr(v11);
            size_t r0 = (size_t)row * N, r1 = (size_t)(row + 8) * N;
            *(float2*)(Chi + r0 + col) = make_float2(h00, h01);
            *(float2*)(Chi + r1 + col) = make_float2(h10, h11);
            *(float2*)(Clo + r0 + col) = make_float2(tfr(v00 - h00), tfr(v01 - h01));
            *(float2*)(Clo + r1 + col) = make_float2(tfr(v10 - h10), tfr(v11 - h11));
        }
}

// ---------------- attention: 128-q rows, 512 threads, 2 barriers/j-tile ----------------
// warp w: rows (w&7)*16, cols (w>>3)*32. Dq-hi in regs, Dq-lo persistent smem,
// S in its own smem region (no overlay). Issue-after-barrier double buffering.
#define PK 68
#define PPV 72
#define ASTG (64*PK*2 + 64*PPV)      // 13312 floats per stage
#define DQLO (2*ASTG)                // Dq-lo tile (128*PK)
#define SOFF (DQLO + 128*PK)         // S tile (128*PK)
__global__ __launch_bounds__(512, 1) void attn_mma() {
    extern __shared__ float sm[];
    const int tid = threadIdx.x, w = tid >> 5, lane = tid & 31;
    const int g = lane >> 2, t = lane & 3;
    const int mrow = (w & 7) * 16, ncol = (w >> 3) * 32;
    const int qt = blockIdx.x, bh = blockIdx.y;
    const int b = bh >> 4, h = bh & 15, q0 = qt * 128;

    const size_t base = (size_t)b * SS * HH + h * HDD;
    const float* Dh = g_Dhi + base;
    const float* Dl = g_Dlo + base;
    const float* Vp = g_V + base;
    float* sDqlo = sm + DQLO;
    float* sS    = sm + SOFF;

    // persistent Dq-lo tile: 128 x 64
    {
        const int lr2 = tid >> 2, lc2 = (tid & 3) * 16;
        const float* src = Dl + (size_t)(q0 + lr2) * HH + lc2;
        #pragma unroll
        for (int u = 0; u < 16; u += 4)
            *(float4*)&sDqlo[lr2 * PK + lc2 + u] = *(const float4*)(src + u);
    }

    // Dq-hi fragments in registers
    uint32_t qhi[8][4];
    {
        const size_t r0g = (size_t)(q0 + mrow + g) * HH;
        const size_t r1g = (size_t)(q0 + mrow + g + 8) * HH;
        #pragma unroll
        for (int c = 0; c < 8; c++) {
            int o = c * 8;
            qhi[c][0] = __float_as_uint(Dh[r0g + o + t]);
            qhi[c][1] = __float_as_uint(Dh[r1g + o + t]);
            qhi[c][2] = __float_as_uint(Dh[r0g + o + t + 4]);
            qhi[c][3] = __float_as_uint(Dh[r1g + o + t + 4]);
        }
    }

    float oacc[4][4];
    #pragma unroll
    for (int i = 0; i < 4; i++)
        #pragma unroll
        for (int j = 0; j < 4; j++) oacc[i][j] = 0.f;

    const int lr = tid >> 3, lc8 = (tid & 7) * 8;
    auto issue = [&](int jt, int s) {
        float* st = sm + s * ASTG;
        const float* srcH = Dh + (size_t)(jt * 64 + lr) * HH + lc8;
        const float* srcL = Dl + (size_t)(jt * 64 + lr) * HH + lc8;
        const float* srcV = Vp + (size_t)(jt * 64 + lr) * HH + lc8;
        cp16(st + lr * PK + lc8,                srcH);
        cp16(st + lr * PK + lc8 + 4,            srcH + 4);
        cp16(st + 64*PK + lr * PK + lc8,        srcL);
        cp16(st + 64*PK + lr * PK + lc8 + 4,    srcL + 4);
        cp16(st + 2*64*PK + lr * PPV + lc8,     srcV);
        cp16(st + 2*64*PK + lr * PPV + lc8 + 4, srcV + 4);
    };

    const int jt0 = 2 * qt;
    int buf = 0;
    issue(jt0, 0); cp_commit();
    for (int jt = jt0; jt < SS / 64; jt++) {
        cp_wait<0>();
        __syncthreads();   // stage data ready; all warps past prev PV (S + peer buf free)
        if (jt + 1 < SS / 64) { issue(jt + 1, buf ^ 1); }
        cp_commit();
        const float* st  = sm + buf * ASTG;
        const float* sKh = st;
        const float* sKl = st + 64 * PK;
        const float* sV  = st + 2 * 64 * PK;
        const int j0 = jt * 64;

        // score = Dq@Dk^T (3-mma tf32x2)
        float sacc[4][4];
        #pragma unroll
        for (int i = 0; i < 4; i++)
            #pragma unroll
            for (int j = 0; j < 4; j++) sacc[i][j] = 0.f;

        #pragma unroll
        for (int c = 0; c < 8; c++) {
            int o = c * 8;
            uint32_t ql[4];
            ql[0] = __float_as_uint(sDqlo[(mrow + g) * PK + o + t]);
            ql[1] = __float_as_uint(sDqlo[(mrow + g + 8) * PK + o + t]);
            ql[2] = __float_as_uint(sDqlo[(mrow + g) * PK + o + t + 4]);
            ql[3] = __float_as_uint(sDqlo[(mrow + g + 8) * PK + o + t + 4]);
            #pragma unroll
            for (int nt = 0; nt < 4; nt++) {
                int jr = (ncol + nt * 8 + g) * PK;
                uint32_t bh0 = __float_as_uint(sKh[jr + o + t]);
                uint32_t bh1 = __float_as_uint(sKh[jr + o + t + 4]);
                uint32_t bl0 = __float_as_uint(sKl[jr + o + t]);
                uint32_t bl1 = __float_as_uint(sKl[jr + o + t + 4]);
                mma8(sacc[nt], qhi[c], bh0, bh1);
                mma8(sacc[nt], qhi[c], bl0, bl1);
                mma8(sacc[nt], ql,     bh0, bh1);
            }
        }

        // mask (strict upper) + exp + pre-round, write S (own region, own rows)
        const int r0 = q0 + mrow + g;
        #pragma unroll
        for (int nt = 0; nt < 4; nt++) {
            int colb = j0 + ncol + nt * 8 + 2 * t;
            float s0 = (colb     > r0    ) ? tfr(__expf(-0.5f * sacc[nt][0])) : 0.f;
            float s1 = (colb + 1 > r0    ) ? tfr(__expf(-0.5f * sacc[nt][1])) : 0.f;
            float s2 = (colb     > r0 + 8) ? tfr(__expf(-0.5f * sacc[nt][2])) : 0.f;
            float s3 = (colb + 1 > r0 + 8) ? tfr(__expf(-0.5f * sacc[nt][3])) : 0.f;
            int cb = ncol + nt * 8 + 2 * t;
            *(float2*)&sS[(mrow + g) * PK + cb]     = make_float2(s0, s1);
            *(float2*)&sS[(mrow + g + 8) * PK + cb] = make_float2(s2, s3);
        }
        __syncthreads();   // S complete across warps

        // PV: oacc += S @ V  (plain tf32)
        #pragma unroll
        for (int c = 0; c < 8; c++) {
            int k = c * 8;
            uint32_t a[4];
            a[0] = __float_as_uint(sS[(mrow + g) * PK + k + t]);
            a[1] = __float_as_uint(sS[(mrow + g + 8) * PK + k + t]);
            a[2] = __float_as_uint(sS[(mrow + g) * PK + k + t + 4]);
            a[3] = __float_as_uint(sS[(mrow + g + 8) * PK + k + t + 4]);
            #pragma unroll
            for (int nt = 0; nt < 4; nt++) {
                int dbc = ncol + nt * 8;
                uint32_t b0 = __float_as_uint(sV[(k + t) * PPV + dbc + g]);
                uint32_t b1 = __float_as_uint(sV[(k + t + 4) * PPV + dbc + g]);
                mma8(oacc[nt], a, b0, b1);
            }
        }
        buf ^= 1;
    }

    // write ctx pre-rounded (O GEMM consumes tf32 directly)
    float* Cb = g_C + base;
    #pragma unroll
    for (int nt = 0; nt < 4; nt++) {
        int col = ncol + nt * 8 + 2 * t;
        *(float2*)(Cb + (size_t)(q0 + mrow + g) * HH + col) =
            make_float2(tfr(oacc[nt][0]), tfr(oacc[nt][1]));
        *(float2*)(Cb + (size_t)(q0 + mrow + g + 8) * HH + col) =
            make_float2(tfr(oacc[nt][2]), tfr(oacc[nt][3]));
    }
}

// ---------------------------------------------------------------------------
extern "C" void kernel_launch(void* const* d_in, const int* in_sizes, int n_in,
                              void* d_out, int out_size) {
    const float* x  = (const float*)d_in[0];
    const float* Wq = (const float*)d_in[1];
    const float* bq = (const float*)d_in[2];
    const float* Wk = (const float*)d_in[3];
    const float* bk = (const float*)d_in[4];
    const float* Wv = (const float*)d_in[5];
    const float* bv = (const float*)d_in[6];
    const float* Wo = (const float*)d_in[7];
    const float* bo = (const float*)d_in[8];
    float* out = (float*)d_out;

    float *pxhi, *pxlo, *pWdThi, *pWdTlo, *pWvT, *pWoT, *pbd, *pDhi, *pDlo, *pV, *pC;
    cudaGetSymbolAddress((void**)&pxhi, g_xhi);
    cudaGetSymbolAddress((void**)&pxlo, g_xlo);
    cudaGetSymbolAddress((void**)&pWdThi, g_WdThi);
    cudaGetSymbolAddress((void**)&pWdTlo, g_WdTlo);
    cudaGetSymbolAddress((void**)&pWvT, g_WvT);
    cudaGetSymbolAddress((void**)&pWoT, g_WoT);
    cudaGetSymbolAddress((void**)&pbd, g_bd);
    cudaGetSymbolAddress((void**)&pDhi, g_Dhi);
    cudaGetSymbolAddress((void**)&pDlo, g_Dlo);
    cudaGetSymbolAddress((void**)&pV, g_V);
    cudaGetSymbolAddress((void**)&pC, g_C);

    const int smem_plain = 3 * 2 * 128 * GP * sizeof(float);          // 36864
    const int smem_split = 3 * 4 * 128 * GP * sizeof(float);          // 73728
    const int smem_attn  = (2 * ASTG + 2 * 128 * PK) * sizeof(float); // 176128
    static bool attr_set = false;
    if (!attr_set) {
        cudaFuncSetAttribute(gemm_split, cudaFuncAttributeMaxDynamicSharedMemorySize, smem_split);
        cudaFuncSetAttribute(gemm_plain<true>,  cudaFuncAttributeMaxDynamicSharedMemorySize, smem_plain);
        cudaFuncSetAttribute(gemm_plain<false>, cudaFuncAttributeMaxDynamicSharedMemorySize, smem_plain);
        cudaFuncSetAttribute(attn_mma, cudaFuncAttributeMaxDynamicSharedMemorySize, smem_attn);
        attr_set = true;
    }

    prep_x<<<MT*HH/256, 256>>>(x, bq, bk);
    prep_w<<<dim3(32, 32, 3), 256>>>(Wq, Wk, Wv, Wo);

    dim3 gg(HH/128, MT/128);  // (8, 32)
    gemm_split<<<gg, 256, smem_split>>>(pxhi, pxlo, pWdThi, pWdTlo, pbd, pDhi, pDlo);
    gemm_plain<true><<<gg, 256, smem_plain>>>(pxhi, pWvT, bv, pV);

    attn_mma<<<dim3(SS/128, BB*NHH), 512, smem_attn>>>();

    gemm_plain<false><<<gg, 256, smem_plain>>>(pC, pWoT, bo, out);
}